// round 1
// baseline (speedup 1.0000x reference)
#include <cuda_runtime.h>

// WaveletTransformLayer: 7-level db4 DWT -> soft threshold -> IDWT, fused.
// One CTA per row; entire pipeline in shared memory; HBM touched exactly twice.

#define NROWS 32768
#define N0    1116
#define NTHREADS 128

// DEC_LO as given; DEC_HI[i] = (-1)^(i+1) * DEC_LO[7-i]
static __constant__ float DLO[8] = {
    -0.010597401784997278f,  0.032883011666982945f,  0.030841381835986965f,
    -0.18703481171888114f,  -0.02798376941698385f,   0.6308807679295904f,
     0.7148465705525415f,    0.23037781330885523f
};
static __constant__ float DHI[8] = {
    -0.23037781330885523f,   0.7148465705525415f,   -0.6308807679295904f,
    -0.02798376941698385f,   0.18703481171888114f,   0.030841381835986965f,
    -0.032883011666982945f, -0.010597401784997278f
};

__device__ __forceinline__ float soft(float c, float thr) {
    return copysignf(fmaxf(fabsf(c) - thr, 0.0f), c);
}

__global__ __launch_bounds__(NTHREADS)
void wavelet_fused_kernel(const float* __restrict__ x,
                          const float* __restrict__ rawthr,
                          float* __restrict__ out)
{
    // Level lengths: m = (n+7)/2
    // {1116, 561, 284, 145, 76, 41, 24, 15}
    __shared__ float sA[1120];   // ping buffer (max 1116)
    __shared__ float sB[576];    // pong buffer (max 562)
    __shared__ float sD[1152];   // detail storage (561+284+145+76+41+24+15 = 1146)

    const int row = blockIdx.x;
    const int tid = threadIdx.x;
    const float thr = fmaxf(rawthr[0], 0.01f);

    // ---- load row (coalesced float4: 1116 = 279*4, row stride 4464B is 16B aligned)
    {
        const float4* __restrict__ xin = (const float4*)(x + (size_t)row * N0);
        float4* sA4 = (float4*)sA;
        #pragma unroll
        for (int i = tid; i < N0 / 4; i += NTHREADS) sA4[i] = xin[i];
    }
    __syncthreads();

    const int lens[8] = {1116, 561, 284, 145, 76, 41, 24, 15};
    const int doff[7] = {0, 561, 845, 990, 1066, 1107, 1131};

    float* bufs[2] = {sA, sB};

    // ---- forward DWT cascade (7 levels). Details soft-thresholded at write.
    #pragma unroll 1
    for (int l = 0; l < 7; l++) {
        const float* __restrict__ a  = bufs[l & 1];
        float* __restrict__ an       = bufs[(l + 1) & 1];
        float* __restrict__ d        = sD + doff[l];
        const int n = lens[l];
        const int m = lens[l + 1];
        const bool last = (l == 6);
        for (int j = tid; j < m; j += NTHREADS) {
            float ca = 0.0f, cd = 0.0f;
            const int base = 2 * j - 6;
            #pragma unroll
            for (int k = 0; k < 8; k++) {
                const int q = base + k;
                const float v = (q >= 0 && q < n) ? a[q] : 0.0f;
                ca = fmaf(v, DLO[7 - k], ca);
                cd = fmaf(v, DHI[7 - k], cd);
            }
            an[j] = last ? soft(ca, thr) : ca;   // approx coeffs thresholded only at final level
            d[j]  = soft(cd, thr);
        }
        __syncthreads();
    }
    // ca7 (len 15, thresholded) now sits in bufs[1] = sB.

    // ---- inverse DWT cascade (7 levels)
    // step r: detail level ld = 6-r, md = lens[ld+1]; out length 2*md-6.
    // a is implicitly truncated to md by the idx < md bound (matches reference copy/slice).
    #pragma unroll 1
    for (int r = 0; r < 7; r++) {
        const int ld = 6 - r;
        const float* __restrict__ d = sD + doff[ld];
        const int md = lens[ld + 1];
        const float* __restrict__ a = bufs[(r + 1) & 1];
        float* __restrict__ o       = bufs[r & 1];
        const int olen = 2 * md - 6;
        for (int t = tid; t < olen; t += NTHREADS) {
            const int off  = 1 - (t & 1);            // t even -> odd taps, t odd -> even taps
            const int base = (t + off - 1) >> 1;
            float s = 0.0f;
            #pragma unroll
            for (int j2 = 0; j2 < 4; j2++) {
                const int idx = base + j2;
                if (idx < md) {
                    const int k = 2 * j2 + off;
                    s = fmaf(a[idx], DLO[k], s);
                    s = fmaf(d[idx], DHI[k], s);
                }
            }
            o[t] = s;
        }
        __syncthreads();
    }
    // Final reconstruction (len 1116) is in bufs[6&1] = sA.

    // ---- store row (coalesced float4)
    {
        float4* __restrict__ oout = (float4*)(out + (size_t)row * N0);
        const float4* sA4 = (const float4*)sA;
        #pragma unroll
        for (int i = tid; i < N0 / 4; i += NTHREADS) oout[i] = sA4[i];
    }
}

extern "C" void kernel_launch(void* const* d_in, const int* in_sizes, int n_in,
                              void* d_out, int out_size)
{
    const float* x      = (const float*)d_in[0];
    const float* rthr   = (const float*)d_in[1];
    float* out          = (float*)d_out;
    wavelet_fused_kernel<<<NROWS, NTHREADS>>>(x, rthr, out);
}

// round 2
// speedup vs baseline: 2.9623x; 2.9623x over previous
#include <cuda_runtime.h>

// 7-level db4 DWT -> soft threshold -> IDWT, fully fused in SMEM.
// One CTA per row. Zero-padded halos remove all bounds checks; vectorized
// LDS/STS; tiny middle levels run in a single warp with __syncwarp only.

#define NTHREADS 128
#define NROWS    32768
#define N0       1116

static __constant__ float DLO[8] = {
    -0.010597401784997278f,  0.032883011666982945f,  0.030841381835986965f,
    -0.18703481171888114f,  -0.02798376941698385f,   0.6308807679295904f,
     0.7148465705525415f,    0.23037781330885523f
};
static __constant__ float DHI[8] = {
    -0.23037781330885523f,   0.7148465705525415f,   -0.6308807679295904f,
    -0.02798376941698385f,   0.18703481171888114f,   0.030841381835986965f,
    -0.032883011666982945f, -0.010597401784997278f
};

__device__ __forceinline__ float softf(float c, float t) {
    return copysignf(fmaxf(fabsf(c) - t, 0.0f), c);
}

// Forward DWT level producing M outputs. Input read from buffer start (physical),
// output pairs written at physical base+6, details at dphys (even base).
// Zero-fills logical [M, 2*PAD) of the output so the next level needs no bounds checks.
template<int M, bool LAST, int NTH>
__device__ __forceinline__ void fwd_level(const float* __restrict__ a,
                                          float* __restrict__ an,
                                          float* __restrict__ dph,
                                          float thr, int tid)
{
    constexpr int PAIRS = (M + 1) / 2;
    constexpr int PAD   = PAIRS + 8;     // extra pairs store zeros (halo for next level)
    for (int t = tid; t < PAD; t += NTH) {
        const float4 v0 = *(const float4*)(a + 4 * t);
        const float4 v1 = *(const float4*)(a + 4 * t + 4);
        const float4 v2 = *(const float4*)(a + 4 * t + 8);
        const float r[12] = {v0.x, v0.y, v0.z, v0.w,
                             v1.x, v1.y, v1.z, v1.w,
                             v2.x, v2.y, v2.z, v2.w};
        float ca0 = 0.f, cd0 = 0.f, ca1 = 0.f, cd1 = 0.f;
        #pragma unroll
        for (int k = 0; k < 8; k++) {
            ca0 = fmaf(r[k],     DLO[7 - k], ca0);
            cd0 = fmaf(r[k],     DHI[7 - k], cd0);
            ca1 = fmaf(r[k + 2], DLO[7 - k], ca1);
            cd1 = fmaf(r[k + 2], DHI[7 - k], cd1);
        }
        cd0 = softf(cd0, thr);
        cd1 = softf(cd1, thr);
        if (LAST) { ca0 = softf(ca0, thr); ca1 = softf(ca1, thr); }
        const int j0 = 2 * t;
        float2 an2 = make_float2(j0 < M ? ca0 : 0.f, (j0 + 1) < M ? ca1 : 0.f);
        *(float2*)(an + 6 + j0) = an2;                 // always: zero-fill halo
        if (j0 < M) {
            float2 dd2 = make_float2(cd0, (j0 + 1) < M ? cd1 : 0.f);
            *(float2*)(dph + j0) = dd2;                // one pad slot per odd-M level
        }
    }
}

// Inverse DWT level: a,d logical length MD -> output length 2*MD-6.
// a,d are logical base pointers at even physical offsets; o is 16B-aligned.
// Proven: every used index is in [0, MD-1]; vector overshoot feeds only
// unstored lanes, so no bounds checks and no zero-fill needed.
template<int MD, int NTH>
__device__ __forceinline__ void inv_level(const float* __restrict__ a,
                                          const float* __restrict__ d,
                                          float* __restrict__ o,
                                          int tid)
{
    constexpr int OLEN  = 2 * MD - 6;
    constexpr int QUADS = (OLEN + 3) / 4;
    for (int u = tid; u < QUADS; u += NTH) {
        const int s = 2 * u;
        const float2 a01 = *(const float2*)(a + s);
        const float2 a23 = *(const float2*)(a + s + 2);
        const float  a4  = a[s + 4];
        const float2 d01 = *(const float2*)(d + s);
        const float2 d23 = *(const float2*)(d + s + 2);
        const float  d4  = d[s + 4];
        // t = 4u + {0,1,2,3}; even t -> odd taps, odd t -> even taps
        float o0 = a01.x * DLO[1];  o0 = fmaf(a01.y, DLO[3], o0);
        o0 = fmaf(a23.x, DLO[5], o0); o0 = fmaf(a23.y, DLO[7], o0);
        o0 = fmaf(d01.x, DHI[1], o0); o0 = fmaf(d01.y, DHI[3], o0);
        o0 = fmaf(d23.x, DHI[5], o0); o0 = fmaf(d23.y, DHI[7], o0);

        float o1 = a01.x * DLO[0];  o1 = fmaf(a01.y, DLO[2], o1);
        o1 = fmaf(a23.x, DLO[4], o1); o1 = fmaf(a23.y, DLO[6], o1);
        o1 = fmaf(d01.x, DHI[0], o1); o1 = fmaf(d01.y, DHI[2], o1);
        o1 = fmaf(d23.x, DHI[4], o1); o1 = fmaf(d23.y, DHI[6], o1);

        float o2 = a01.y * DLO[1];  o2 = fmaf(a23.x, DLO[3], o2);
        o2 = fmaf(a23.y, DLO[5], o2); o2 = fmaf(a4,    DLO[7], o2);
        o2 = fmaf(d01.y, DHI[1], o2); o2 = fmaf(d23.x, DHI[3], o2);
        o2 = fmaf(d23.y, DHI[5], o2); o2 = fmaf(d4,    DHI[7], o2);

        float o3 = a01.y * DLO[0];  o3 = fmaf(a23.x, DLO[2], o3);
        o3 = fmaf(a23.y, DLO[4], o3); o3 = fmaf(a4,    DLO[6], o3);
        o3 = fmaf(d01.y, DHI[0], o3); o3 = fmaf(d23.x, DHI[2], o3);
        o3 = fmaf(d23.y, DHI[4], o3); o3 = fmaf(d4,    DHI[6], o3);

        if (4 * u + 3 < OLEN) {
            *(float4*)(o + 4 * u) = make_float4(o0, o1, o2, o3);
        } else {
            // OLEN % 4 == 2 tail: exactly two valid outputs
            *(float2*)(o + 4 * u) = make_float2(o0, o1);
        }
    }
}

__global__ __launch_bounds__(NTHREADS)
void wavelet_fused_kernel(const float* __restrict__ x,
                          const float* __restrict__ rawthr,
                          float* __restrict__ out)
{
    // Level lengths: {1116, 561, 284, 145, 76, 41, 24, 15}
    __shared__ __align__(16) float sA[1168];
    __shared__ __align__(16) float sB[640];
    __shared__ __align__(16) float sD[1152];  // detail offsets: 0,562,846,992,1068,1110,1134

    const int row = blockIdx.x;
    const int tid = threadIdx.x;
    const float thr = fmaxf(rawthr[0], 0.01f);

    // ---- zero halos + load row (logical x[i] at sA[6+i])
    {
        const float4 z4 = make_float4(0.f, 0.f, 0.f, 0.f);
        #pragma unroll
        for (int i = tid; i < 640 / 4; i += NTHREADS) ((float4*)sB)[i] = z4;
        if (tid < 6) sA[tid] = 0.f;
        for (int i = 1122 + tid; i < 1168; i += NTHREADS) sA[i] = 0.f;

        const float4* __restrict__ xin = (const float4*)(x + (size_t)row * N0);
        #pragma unroll
        for (int q = tid; q < N0 / 4; q += NTHREADS) {
            const float4 v = xin[q];
            *(float2*)(sA + 6 + 4 * q) = make_float2(v.x, v.y);
            *(float2*)(sA + 8 + 4 * q) = make_float2(v.z, v.w);
        }
    }
    __syncthreads();

    // ---- forward DWT, big levels (128 threads)
    fwd_level<561, false, NTHREADS>(sA, sB, sD + 0,   thr, tid); __syncthreads();
    fwd_level<284, false, NTHREADS>(sB, sA, sD + 562, thr, tid); __syncthreads();
    fwd_level<145, false, NTHREADS>(sA, sB, sD + 846, thr, tid); __syncthreads();
    fwd_level<76,  false, NTHREADS>(sB, sA, sD + 992, thr, tid); __syncthreads();

    // ---- tiny levels: single warp, __syncwarp only
    if (tid < 32) {
        fwd_level<41, false, 32>(sA, sB, sD + 1068, thr, tid); __syncwarp();
        fwd_level<24, false, 32>(sB, sA, sD + 1110, thr, tid); __syncwarp();
        fwd_level<15, true,  32>(sA, sB, sD + 1134, thr, tid); __syncwarp();
        inv_level<15, 32>(sB + 6, sD + 1134, sA + 8, tid);     __syncwarp();
        inv_level<24, 32>(sA + 8, sD + 1110, sB + 8, tid);     __syncwarp();
        inv_level<41, 32>(sB + 8, sD + 1068, sA + 8, tid);
    }
    __syncthreads();

    // ---- inverse DWT, big levels (128 threads)
    inv_level<76,  NTHREADS>(sA + 8, sD + 992, sB + 8, tid); __syncthreads();
    inv_level<145, NTHREADS>(sB + 8, sD + 846, sA + 8, tid); __syncthreads();
    inv_level<284, NTHREADS>(sA + 8, sD + 562, sB + 8, tid); __syncthreads();
    inv_level<561, NTHREADS>(sB + 8, sD + 0,   sA + 8, tid); __syncthreads();

    // ---- store row (final result at sA+8, 16B-aligned)
    {
        float4* __restrict__ oout = (float4*)(out + (size_t)row * N0);
        const float4* sO4 = (const float4*)(sA + 8);
        #pragma unroll
        for (int q = tid; q < N0 / 4; q += NTHREADS) oout[q] = sO4[q];
    }
}

extern "C" void kernel_launch(void* const* d_in, const int* in_sizes, int n_in,
                              void* d_out, int out_size)
{
    const float* x    = (const float*)d_in[0];
    const float* rthr = (const float*)d_in[1];
    float* out        = (float*)d_out;
    wavelet_fused_kernel<<<NROWS, NTHREADS>>>(x, rthr, out);
}